// round 12
// baseline (speedup 1.0000x reference)
#include <cuda_runtime.h>
#include <cuda_bf16.h>
#include <math.h>
#include <stdint.h>

// ---------------------------------------------------------------------------
// BitNetV3 MLP via IMMA (mma.sync.m16n8k32.s8) + cp.async.bulk tile loads.
// out = BitLinear(silu(BitLinear(x,Wg)) * BitLinear(x,Wu), Wd)
// All operands pre-packed into tile-major, SW128-swizzled 16KB chunks:
//   tile(mt, kc) at byte ((mt*nC)+kc)*16384 ; within: sw(row*128 + col)
// so each GEMM K-chunk load is ONE bulk copy per matrix (no LDGSTS issue wall).
// T=4096 tokens, H=2048, I=8192. Integer GEMM math is bit-exact.
// ---------------------------------------------------------------------------

#define T_TOK 4096
#define H_DIM 2048
#define I_DIM 8192

#define NORM_2048 0.022097086912079608f   // 1/sqrt(2048)
#define NORM_8192 0.011048543456039804f   // 1/sqrt(8192)

// ------------------------- scratch (allocation-free) -----------------------
__device__ __align__(16) int    g_qx1[T_TOK * H_DIM / 4];            //  8 MB
__device__ __align__(16) int    g_qx2[T_TOK * I_DIM / 4];            // 32 MB
__device__ float  g_as1[T_TOK];
__device__ float  g_as2[T_TOK];
__device__ __align__(16) int    g_qwg[I_DIM * H_DIM / 4];            // 16 MB
__device__ __align__(16) int    g_qwu[I_DIM * H_DIM / 4];            // 16 MB
__device__ __align__(16) int    g_qwd[H_DIM * I_DIM / 4];            // 16 MB
__device__ float  g_ws[4];
__device__ float  g_part[3 * 512];
__device__ float  g_gate[(size_t)T_TOK * I_DIM];                     // 128 MB

// ----------------------------- PTX helpers ---------------------------------
__device__ __forceinline__ uint32_t s2u(const void* p) {
    uint32_t a;
    asm("{ .reg .u64 t; cvta.to.shared.u64 t, %1; cvt.u32.u64 %0, t; }"
        : "=r"(a) : "l"(p));
    return a;
}
__device__ __forceinline__ void bulk_g2s(uint32_t dst, const void* src,
                                         uint32_t bytes, uint32_t mbar) {
    asm volatile(
        "cp.async.bulk.shared::cta.global.mbarrier::complete_tx::bytes "
        "[%0], [%1], %2, [%3];"
        :: "r"(dst), "l"(src), "r"(bytes), "r"(mbar) : "memory");
}
__device__ __forceinline__ void mbar_init(uint32_t a, uint32_t c) {
    asm volatile("mbarrier.init.shared.b64 [%0], %1;" :: "r"(a), "r"(c) : "memory");
}
__device__ __forceinline__ void mbar_expect_tx(uint32_t a, uint32_t bytes) {
    asm volatile("mbarrier.arrive.expect_tx.shared.b64 _, [%0], %1;"
                 :: "r"(a), "r"(bytes) : "memory");
}
__device__ __forceinline__ void mbar_wait(uint32_t a, uint32_t ph) {
    asm volatile(
        "{\n.reg .pred P;\n"
        "W%=:\n"
        "mbarrier.try_wait.parity.acquire.cta.shared::cta.b64 P, [%0], %1, 0x989680;\n"
        "@P bra D%=;\n"
        "bra W%=;\n"
        "D%=:\n}" :: "r"(a), "r"(ph) : "memory");
}
__device__ __forceinline__ void ldm_x4(uint32_t* r, uint32_t addr) {
    asm volatile("ldmatrix.sync.aligned.m8n8.x4.shared.b16 {%0,%1,%2,%3}, [%4];"
                 : "=r"(r[0]), "=r"(r[1]), "=r"(r[2]), "=r"(r[3]) : "r"(addr));
}
__device__ __forceinline__ void mma_s8(int* d, const uint32_t* a,
                                       uint32_t b0, uint32_t b1) {
    asm volatile(
        "mma.sync.aligned.m16n8k32.row.col.s32.s8.s8.s32 "
        "{%0,%1,%2,%3}, {%4,%5,%6,%7}, {%8,%9}, {%0,%1,%2,%3};"
        : "+r"(d[0]), "+r"(d[1]), "+r"(d[2]), "+r"(d[3])
        : "r"(a[0]), "r"(a[1]), "r"(a[2]), "r"(a[3]), "r"(b0), "r"(b1));
}

// --------------- batched weight prep (3 weights in 3 launches) -------------
__global__ void abs_sum_all(const float4* __restrict__ w0,
                            const float4* __restrict__ w1,
                            const float4* __restrict__ w2,
                            int n4, float* __restrict__ part) {
    const float4* w = (blockIdx.y == 0) ? w0 : (blockIdx.y == 1) ? w1 : w2;
    float s0 = 0.f, s1 = 0.f, s2 = 0.f, s3 = 0.f;
    int i = blockIdx.x * 256 + threadIdx.x;
    const int stride = 512 * 256;
    for (; i + 3 * stride < n4; i += 4 * stride) {
        float4 a = w[i];
        float4 b = w[i + stride];
        float4 c = w[i + 2 * stride];
        float4 d = w[i + 3 * stride];
        s0 += fabsf(a.x) + fabsf(a.y) + fabsf(a.z) + fabsf(a.w);
        s1 += fabsf(b.x) + fabsf(b.y) + fabsf(b.z) + fabsf(b.w);
        s2 += fabsf(c.x) + fabsf(c.y) + fabsf(c.z) + fabsf(c.w);
        s3 += fabsf(d.x) + fabsf(d.y) + fabsf(d.z) + fabsf(d.w);
    }
    for (; i < n4; i += stride) {
        float4 a = w[i];
        s0 += fabsf(a.x) + fabsf(a.y) + fabsf(a.z) + fabsf(a.w);
    }
    __shared__ float red[256];
    red[threadIdx.x] = (s0 + s1) + (s2 + s3);
    __syncthreads();
    for (int off = 128; off > 0; off >>= 1) {
        if ((int)threadIdx.x < off) red[threadIdx.x] += red[threadIdx.x + off];
        __syncthreads();
    }
    if (threadIdx.x == 0) part[blockIdx.y * 512 + blockIdx.x] = red[0];
}

__global__ void abs_final_all(const float* __restrict__ part, long long n,
                              float* __restrict__ ws) {
    __shared__ double red[256];
    double s = 0.0;
    for (int i = threadIdx.x; i < 512; i += 256)
        s += (double)part[blockIdx.x * 512 + i];
    red[threadIdx.x] = s;
    __syncthreads();
    for (int off = 128; off > 0; off >>= 1) {
        if ((int)threadIdx.x < off) red[threadIdx.x] += red[threadIdx.x + off];
        __syncthreads();
    }
    if (threadIdx.x == 0)
        ws[blockIdx.x] = fmaxf((float)(red[0] / (double)n), 1e-5f);
}

// ternary quantize + pack into tile-major swizzled layout
__global__ void quant_pack_all(const float* __restrict__ w0,
                               const float* __restrict__ w1,
                               const float* __restrict__ w2,
                               const float* __restrict__ sc,
                               int* __restrict__ q0, int* __restrict__ q1,
                               int* __restrict__ q2, int n4) {
    int i = blockIdx.x * 256 + threadIdx.x;
    if (i >= n4) return;
    const int which = blockIdx.y;
    const float* w = (which == 0) ? w0 : (which == 1) ? w1 : w2;
    char* qb = (char*)((which == 0) ? q0 : (which == 1) ? q1 : q2);
    const int Kd4 = (which == 2) ? (I_DIM / 4) : (H_DIM / 4);  // int32 per row
    const int nC  = (which == 2) ? (I_DIM / 128) : (H_DIM / 128);
    float s = sc[which];
    float4 v = reinterpret_cast<const float4*>(w)[i];
    int a = (int)fminf(fmaxf(rintf(v.x / s), -1.f), 1.f);
    int b = (int)fminf(fmaxf(rintf(v.y / s), -1.f), 1.f);
    int c = (int)fminf(fmaxf(rintf(v.z / s), -1.f), 1.f);
    int d = (int)fminf(fmaxf(rintf(v.w / s), -1.f), 1.f);
    int packed = (a & 0xFF) | ((b & 0xFF) << 8) | ((c & 0xFF) << 16) | ((d & 0xFF) << 24);

    const int o  = i / Kd4;          // output row
    const int ic = i - o * Kd4;      // int32 col within row
    const int kc = ic >> 5;          // 128-byte K chunk
    uint32_t off = (uint32_t)((o & 127) * 128 + ((ic >> 2) & 7) * 16);
    off ^= (off >> 3) & 0x70;        // SW128 swizzle
    size_t addr = ((size_t)((o >> 7) * nC + kc) << 14) + off + (ic & 3) * 4;
    *(int*)(qb + addr) = packed;
}

// ----- FWHT (last axis) + per-token int8 quant + pack (tile-major out) -----
template <int N, int TPB>
__global__ void fwht_quant(const float* __restrict__ X, int* __restrict__ Q,
                           float* __restrict__ scales, float norm) {
    __shared__ float s[N];
    __shared__ float red[TPB];
    const int t = blockIdx.x;
    const float* x = X + (size_t)t * N;

    for (int i = threadIdx.x; i < N; i += TPB) s[i] = x[i];
    __syncthreads();

    for (int h = 1; h < N; h <<= 1) {
        for (int p = threadIdx.x; p < N / 2; p += TPB) {
            int i = ((p & ~(h - 1)) << 1) | (p & (h - 1));
            float a = s[i], b = s[i + h];
            s[i] = a + b;
            s[i + h] = a - b;
        }
        __syncthreads();
    }

    float m = 0.f;
    for (int i = threadIdx.x; i < N; i += TPB)
        m = fmaxf(m, fabsf(s[i] * norm));
    red[threadIdx.x] = m;
    __syncthreads();
    for (int off = TPB / 2; off > 0; off >>= 1) {
        if ((int)threadIdx.x < off)
            red[threadIdx.x] = fmaxf(red[threadIdx.x], red[threadIdx.x + off]);
        __syncthreads();
    }
    float scale = 127.f / fmaxf(red[0], 1e-5f);
    if (threadIdx.x == 0) scales[t] = scale;

    // pack into tile-major swizzled layout: tile(mt,kc) 16KB, row = t&127
    char* qb = (char*)Q;
    const int nC = N / 128;
    const size_t rowTile = ((size_t)(t >> 7) * nC) << 14;
    const uint32_t rbase = (uint32_t)((t & 127) * 128);
    for (int i = threadIdx.x; i < N / 4; i += TPB) {
        float v0 = s[4 * i + 0] * norm * scale;
        float v1 = s[4 * i + 1] * norm * scale;
        float v2 = s[4 * i + 2] * norm * scale;
        float v3 = s[4 * i + 3] * norm * scale;
        int q0 = (int)fminf(fmaxf(rintf(v0), -128.f), 127.f);
        int q1 = (int)fminf(fmaxf(rintf(v1), -128.f), 127.f);
        int q2 = (int)fminf(fmaxf(rintf(v2), -128.f), 127.f);
        int q3 = (int)fminf(fmaxf(rintf(v3), -128.f), 127.f);
        int packed = (q0 & 0xFF) | ((q1 & 0xFF) << 8)
                   | ((q2 & 0xFF) << 16) | ((q3 & 0xFF) << 24);
        uint32_t off = rbase + ((i >> 2) & 7) * 16;
        off ^= (off >> 3) & 0x70;
        *(int*)(qb + rowTile + ((size_t)(i >> 5) << 14) + off + (i & 3) * 4) = packed;
    }
}

// ---------------------------- IMMA int8 GEMM -------------------------------
// CTA: 128x128 tile, 8 warps (4M x 2N), warp tile 32x64.
// K chunks are pre-swizzled contiguous 16KB tiles; each chunk load is one
// cp.async.bulk per matrix onto a per-stage mbarrier. 3-stage ring, dist 1.
// C[t,o] = acc * wS / actScale[t]. MODE 1: C holds gate; write silu(gate)*up.
#define STAGE_BYTES 32768
#define GEMM_SMEM   (3 * STAGE_BYTES + 64)

template <int MODE>
__global__ __launch_bounds__(256, 2)
void gemm_imma(const char* __restrict__ A,   // tile-major packed [Mt][nC][16KB]
               const char* __restrict__ Bw,  // tile-major packed [Ot][nC][16KB]
               float* __restrict__ C,        // [M_total][O] f32
               int O, int nC,
               const float* __restrict__ actScale,
               const float* __restrict__ wScale) {
    extern __shared__ __align__(1024) char smem[];
    const uint32_t S0 = s2u(smem);           // stage s: A at +s*32KB, B at +16KB
    const uint32_t MB = S0 + 3 * STAGE_BYTES; // 3 mbarriers (8B each)

    const int tid = threadIdx.x;
    const int lane = tid & 31, w = tid >> 5;
    const int wm = w >> 1, wn = w & 1;        // warp grid 4(M) x 2(N)
    const int blockM = blockIdx.y * 128, blockN = blockIdx.x * 128;

    // ldmatrix lane geometry (SW128: addr = row*128 + (k ^ ((row&7)<<4)))
    const int aRow = wm * 32 + (lane & 7) + ((lane >> 3) & 1) * 8;
    const uint32_t aKh = ((lane >> 4) & 1) * 16;
    const uint32_t aQ  = (uint32_t)(aRow & 7) << 4;
    const int bRow = wn * 64 + (lane & 7) + ((lane >> 4) & 1) * 8;
    const uint32_t bKh = ((lane >> 3) & 1) * 16;
    const uint32_t bQ  = (uint32_t)(bRow & 7) << 4;

    int acc[2][8][4];
#pragma unroll
    for (int i = 0; i < 2; i++)
#pragma unroll
        for (int j = 0; j < 8; j++)
#pragma unroll
            for (int k = 0; k < 4; k++) acc[i][j][k] = 0;

    const char* gA = A  + (((size_t)blockIdx.y * nC) << 14);  // chunks contiguous
    const char* gB = Bw + (((size_t)blockIdx.x * nC) << 14);

    if (tid == 0) {
        mbar_init(MB + 0, 1);
        mbar_init(MB + 8, 1);
        mbar_init(MB + 16, 1);
    }
    __syncthreads();

    // prologue: chunk 0 -> stage 0
    if (tid == 0) {
        mbar_expect_tx(MB + 0, STAGE_BYTES);
        bulk_g2s(S0,         gA, 16384, MB + 0);
        bulk_g2s(S0 + 16384, gB, 16384, MB + 0);
    }

    int st = 0, par = 0;
    for (int c = 0; c < nC; c++) {
        if (c + 1 < nC && tid == 0) {
            int ns = st + 1; if (ns == 3) ns = 0;
            const uint32_t d = S0 + ns * STAGE_BYTES;
            mbar_expect_tx(MB + ns * 8, STAGE_BYTES);
            bulk_g2s(d,         gA + ((size_t)(c + 1) << 14), 16384, MB + ns * 8);
            bulk_g2s(d + 16384, gB + ((size_t)(c + 1) << 14), 16384, MB + ns * 8);
        }
        mbar_wait(MB + st * 8, par);     // chunk c data visible (acquire)

        const uint32_t aBase = S0 + st * STAGE_BYTES + (uint32_t)aRow * 128;
        const uint32_t bBase = S0 + st * STAGE_BYTES + 16384 + (uint32_t)bRow * 128;
#pragma unroll
        for (int ks = 0; ks < 4; ks++) {
            uint32_t Af[2][4], Bf[4][4];
#pragma unroll
            for (int mr = 0; mr < 2; mr++)
                ldm_x4(Af[mr], aBase + mr * (16 * 128)
                               + (((uint32_t)(ks * 32) + aKh) ^ aQ));
#pragma unroll
            for (int ng = 0; ng < 4; ng++)
                ldm_x4(Bf[ng], bBase + ng * (16 * 128)
                               + (((uint32_t)(ks * 32) + bKh) ^ bQ));
#pragma unroll
            for (int mr = 0; mr < 2; mr++)
#pragma unroll
                for (int nb = 0; nb < 8; nb++)
                    mma_s8(acc[mr][nb], Af[mr],
                           Bf[nb >> 1][(nb & 1) * 2],
                           Bf[nb >> 1][(nb & 1) * 2 + 1]);
        }
        __syncthreads();                 // all warps done with stage st
        if (st == 2) par ^= 1;           // parity = (c/3)&1 for next uses
        if (++st == 3) st = 0;
    }

    // ---------------- epilogue: dequant + store (from registers) -----------
    const float wS = wScale[0];
    const int r = lane >> 2, cq = (lane & 3) * 2;
#pragma unroll
    for (int mr = 0; mr < 2; mr++) {
#pragma unroll
        for (int half = 0; half < 2; half++) {
            const int m = blockM + wm * 32 + mr * 16 + half * 8 + r;
            const float f = wS / __ldg(&actScale[m]);
            float* crow = C + (size_t)m * O + blockN + wn * 64;
#pragma unroll
            for (int nb = 0; nb < 8; nb++) {
                float2 v;
                v.x = (float)acc[mr][nb][half * 2]     * f;
                v.y = (float)acc[mr][nb][half * 2 + 1] * f;
                float* p = crow + nb * 8 + cq;
                if (MODE == 1) {
                    float2 g = *reinterpret_cast<const float2*>(p);
                    v.x *= g.x / (1.f + expf(-g.x));
                    v.y *= g.y / (1.f + expf(-g.y));
                }
                *reinterpret_cast<float2*>(p) = v;
            }
        }
    }
}

// ------------------------------- launcher ----------------------------------
extern "C" void kernel_launch(void* const* d_in, const int* in_sizes, int n_in,
                              void* d_out, int out_size) {
    const float* x  = (const float*)d_in[0];
    const float* wg = (const float*)d_in[1];
    const float* wu = (const float*)d_in[2];
    const float* wd = (const float*)d_in[3];
    float* out = (float*)d_out;

    void* p;
    cudaGetSymbolAddress(&p, g_qx1);  int*   qx1  = (int*)p;
    cudaGetSymbolAddress(&p, g_qx2);  int*   qx2  = (int*)p;
    cudaGetSymbolAddress(&p, g_as1);  float* as1  = (float*)p;
    cudaGetSymbolAddress(&p, g_as2);  float* as2  = (float*)p;
    cudaGetSymbolAddress(&p, g_qwg);  int*   qwg  = (int*)p;
    cudaGetSymbolAddress(&p, g_qwu);  int*   qwu  = (int*)p;
    cudaGetSymbolAddress(&p, g_qwd);  int*   qwd  = (int*)p;
    cudaGetSymbolAddress(&p, g_ws);   float* ws   = (float*)p;
    cudaGetSymbolAddress(&p, g_part); float* part = (float*)p;
    cudaGetSymbolAddress(&p, g_gate); float* gate = (float*)p;

    cudaFuncSetAttribute(gemm_imma<0>, cudaFuncAttributeMaxDynamicSharedMemorySize, GEMM_SMEM);
    cudaFuncSetAttribute(gemm_imma<1>, cudaFuncAttributeMaxDynamicSharedMemorySize, GEMM_SMEM);

    const long long nW = (long long)I_DIM * H_DIM;
    const int n4 = (int)(nW / 4);

    // launches 0-2: weight scales + ternary pack into tile layout
    abs_sum_all<<<dim3(512, 3), 256>>>((const float4*)wg, (const float4*)wu,
                                       (const float4*)wd, n4, part);
    abs_final_all<<<3, 256>>>(part, nW, ws);
    quant_pack_all<<<dim3((n4 + 255) / 256, 3), 256>>>(wg, wu, wd, ws,
                                                       qwg, qwu, qwd, n4);

    // launch 3: FWHT(2048) + int8 quant of input (shared by gate & up)
    fwht_quant<H_DIM, 256><<<T_TOK, 256>>>(x, qx1, as1, NORM_2048);

    // launches 4-5: gate = xq@Wg^T, then h = silu(gate)*(xq@Wu^T) fused
    gemm_imma<0><<<dim3(I_DIM / 128, T_TOK / 128), 256, GEMM_SMEM>>>(
        (const char*)qx1, (const char*)qwg, gate, I_DIM, H_DIM / 128, as1, ws + 0);
    gemm_imma<1><<<dim3(I_DIM / 128, T_TOK / 128), 256, GEMM_SMEM>>>(
        (const char*)qx1, (const char*)qwu, gate, I_DIM, H_DIM / 128, as1, ws + 1);

    // launch 6: FWHT(8192) + int8 quant of h (TPB 1024)
    fwht_quant<I_DIM, 1024><<<T_TOK, 1024>>>(gate, qx2, as2, NORM_8192);

    // launch 7: out = hq @ Wd^T
    gemm_imma<0><<<dim3(H_DIM / 128, T_TOK / 128), 256, GEMM_SMEM>>>(
        (const char*)qx2, (const char*)qwd, out, H_DIM, I_DIM / 128, as2, ws + 2);
}